// round 16
// baseline (speedup 1.0000x reference)
#include <cuda_runtime.h>
#include <cuda_bf16.h>
#include <cuda_fp16.h>
#include <stdint.h>

#define DIMC 768
#define NH 12
#define HD 64
#define BSZ 2
#define TLEN 2048
#define MROWS 4096

// score_scale(0.125) * log2(e)
#define QSCALE 0.180336879f
#define ONES_H2 0x3C003C00u

// ---------------- scratch ----------------
__device__ __half g_xq[MROWS * DIMC];
__device__ __half g_xk[MROWS * DIMC];
__device__ __half g_xv[MROWS * DIMC];
__device__ __half g_wq[DIMC * DIMC], g_wk[DIMC * DIMC], g_wv[DIMC * DIMC];
__device__ __half g_wo[DIMC * DIMC];
__device__ __half g_q[MROWS * DIMC], g_k[MROWS * DIMC], g_v[MROWS * DIMC];  // [b,h,t,d]
__device__ __half g_a[MROWS * DIMC];                           // attn out [b,t,c]

// ---------------- helpers ----------------
__device__ __forceinline__ uint32_t smem_u32(const void* p) {
    uint32_t a;
    asm("{ .reg .u64 t; cvta.to.shared.u64 t, %1; cvt.u32.u64 %0, t; }" : "=r"(a) : "l"(p));
    return a;
}
__device__ __forceinline__ void cp16(uint32_t dst, const void* src) {
    asm volatile("cp.async.cg.shared.global [%0], [%1], 16;" :: "r"(dst), "l"(src) : "memory");
}
#define CP_COMMIT() asm volatile("cp.async.commit_group;" ::: "memory")
#define CP_WAIT0()  asm volatile("cp.async.wait_group 0;" ::: "memory")
#define CP_WAIT1()  asm volatile("cp.async.wait_group 1;" ::: "memory")
__device__ __forceinline__ void ldm4(uint32_t* r, uint32_t addr) {
    asm volatile("ldmatrix.sync.aligned.m8n8.x4.shared.b16 {%0,%1,%2,%3}, [%4];"
        : "=r"(r[0]), "=r"(r[1]), "=r"(r[2]), "=r"(r[3]) : "r"(addr));
}
__device__ __forceinline__ void ldm4t(uint32_t* r, uint32_t addr) {
    asm volatile("ldmatrix.sync.aligned.m8n8.x4.trans.shared.b16 {%0,%1,%2,%3}, [%4];"
        : "=r"(r[0]), "=r"(r[1]), "=r"(r[2]), "=r"(r[3]) : "r"(addr));
}
__device__ __forceinline__ void mma_f16(float* c, const uint32_t* a, uint32_t b0, uint32_t b1) {
    asm volatile("mma.sync.aligned.m16n8k16.row.col.f32.f16.f16.f32 "
        "{%0,%1,%2,%3}, {%4,%5,%6,%7}, {%8,%9}, {%0,%1,%2,%3};"
        : "+f"(c[0]), "+f"(c[1]), "+f"(c[2]), "+f"(c[3])
        : "r"(a[0]), "r"(a[1]), "r"(a[2]), "r"(a[3]), "r"(b0), "r"(b1));
}
__device__ __forceinline__ uint32_t packh(float x, float y) {
    __half2 h = __floats2half2_rn(x, y);
    return *(uint32_t*)&h;
}
__device__ __forceinline__ uint32_t ex2_h2(uint32_t x) {
    uint32_t r;
    asm("ex2.approx.f16x2 %0, %1;" : "=r"(r) : "r"(x));
    return r;
}

#define SW128(o) ((uint32_t)(o) ^ ((((uint32_t)(o)) >> 3) & 0x70))

// ====================== merged split kernel =================================
__global__ __launch_bounds__(256)
void split_all_kernel(const float* __restrict__ q_in, const float* __restrict__ k_in,
                      const float* __restrict__ v_in,
                      const float* __restrict__ Wq, const float* __restrict__ Wk,
                      const float* __restrict__ Wv, const float* __restrict__ Wo,
                      __half* xq, __half* xk, __half* xv,
                      __half* wq, __half* wk, __half* wv, __half* wo) {
    int blk = blockIdx.x;
    const float* s;
    __half* d;
    int i;
    if (blk < 9216) {
        int z = blk / 3072;
        i = (blk % 3072) * 256 + threadIdx.x;
        s = z == 0 ? q_in : z == 1 ? k_in : v_in;
        d = z == 0 ? xq : z == 1 ? xk : xv;
    } else {
        int wb = blk - 9216;
        int z = wb / 576;
        i = (wb % 576) * 256 + threadIdx.x;
        s = z == 0 ? Wq : z == 1 ? Wk : z == 2 ? Wv : Wo;
        d = z == 0 ? wq : z == 1 ? wk : z == 2 ? wv : wo;
    }
    float4 v = ((const float4*)s)[i];
    uint2 o = {packh(v.x, v.y), packh(v.z, v.w)};
    ((uint2*)d)[i] = o;
}

// ====================== QKV projection (BK=64, 2-stage, occ 3) ==============
// CTA 128x128, 4 warps (2x2), warp tile 64x64. 12 iterations.
// Stage: A 128x128B (16KB) | W 128x128B (16KB) = 32KB; 2 stages = 64KB.
#define Q2_W   16384
#define Q2_STG 32768
#define Q2_SMEM (2 * Q2_STG)   // 65536

__device__ __forceinline__ void qkv_issue(
    uint32_t stg, const __half* a, const __half* w,
    int row0, int col0, int k0, int tid) {
#pragma unroll
    for (int j = 0; j < 8; j++) {
        int idx = tid + j * 128;
        int r = idx >> 3, ch = idx & 7;
        uint32_t so = SW128(r * 128 + ch * 16);
        cp16(stg + so,        a + (size_t)(row0 + r) * DIMC + k0 + ch * 8);
        cp16(stg + Q2_W + so, w + (size_t)(col0 + r) * DIMC + k0 + ch * 8);
    }
}

__global__ __launch_bounds__(128, 3)
void proj_qkv_kernel(
    const __half* __restrict__ xq, const __half* __restrict__ xk,
    const __half* __restrict__ xv,
    const __half* __restrict__ wq, const __half* __restrict__ wk,
    const __half* __restrict__ wv,
    const float* __restrict__ bq, const float* __restrict__ bk,
    const float* __restrict__ bv,
    __half* __restrict__ oq, __half* __restrict__ ok, __half* __restrict__ ov) {
    extern __shared__ __align__(16) char dsm[];
    const uint32_t sb = smem_u32(dsm);
    const int tid = threadIdx.x;
    const int wid = tid >> 5;
    const int lane = tid & 31;
    const int wm = wid >> 1;
    const int wn = wid & 1;
    const int row0 = blockIdx.x * 128;
    const int col0 = blockIdx.y * 128;
    const int z = blockIdx.z;
    const float oscale = (z == 0) ? QSCALE : 1.f;

    const __half* a  = z == 0 ? xq : z == 1 ? xk : xv;
    const __half* w  = z == 0 ? wq : z == 1 ? wk : wv;
    const float* bias = z == 0 ? bq : z == 1 ? bk : bv;
    __half* op = z == 0 ? oq : z == 1 ? ok : ov;

    float acc[4][8][4];
#pragma unroll
    for (int i = 0; i < 4; i++)
#pragma unroll
        for (int j = 0; j < 8; j++)
#pragma unroll
            for (int k = 0; k < 4; k++) acc[i][j][k] = 0.f;

    const int lrow = (lane & 7) + (lane & 8);
    const int lcb = (lane >> 4) * 16;

    qkv_issue(sb, a, w, row0, col0, 0, tid);
    CP_COMMIT();

    for (int kt = 0; kt < 12; kt++) {
        if (kt < 11) {
            qkv_issue(sb + ((kt + 1) & 1) * Q2_STG, a, w, row0, col0, (kt + 1) * 64, tid);
            CP_COMMIT();
            CP_WAIT1();
        } else {
            CP_WAIT0();
        }
        __syncthreads();
        const uint32_t stg = sb + (kt & 1) * Q2_STG;
#pragma unroll
        for (int ks = 0; ks < 4; ks++) {
            const uint32_t kb = (uint32_t)(ks * 32 + lcb);
            uint32_t af[4][4];
#pragma unroll
            for (int i = 0; i < 4; i++) {
                uint32_t so = SW128((uint32_t)((wm * 64 + i * 16 + lrow) * 128) + kb);
                ldm4(af[i], stg + so);
            }
#pragma unroll
            for (int g = 0; g < 4; g++) {
                uint32_t so = SW128((uint32_t)((wn * 64 + g * 16 + lrow) * 128) + kb);
                uint32_t b4[4];
                ldm4(b4, stg + Q2_W + so);
#pragma unroll
                for (int i = 0; i < 4; i++) {
                    mma_f16(acc[i][2 * g],     af[i], b4[0], b4[2]);
                    mma_f16(acc[i][2 * g + 1], af[i], b4[1], b4[3]);
                }
            }
        }
        __syncthreads();
    }

    // epilogue
#pragma unroll
    for (int i = 0; i < 4; i++) {
        const int m0 = row0 + wm * 64 + i * 16 + (lane >> 2);
#pragma unroll
        for (int j = 0; j < 8; j++) {
            const int c = col0 + wn * 64 + j * 8 + (lane & 3) * 2;
            const int h = c >> 6, d = c & 63;
            float2 bv2 = *(const float2*)&bias[c];
            float v0 = (acc[i][j][0] + bv2.x) * oscale;
            float v1 = (acc[i][j][1] + bv2.y) * oscale;
            float v2 = (acc[i][j][2] + bv2.x) * oscale;
            float v3 = (acc[i][j][3] + bv2.y) * oscale;
            {
                const int gr = m0, b = gr >> 11, t = gr & 2047;
                size_t oi = (((size_t)b * NH + h) * TLEN + t) * HD + d;
                *(uint32_t*)&op[oi] = packh(v0, v1);
            }
            {
                const int gr = m0 + 8, b = gr >> 11, t = gr & 2047;
                size_t oi = (((size_t)b * NH + h) * TLEN + t) * HD + d;
                *(uint32_t*)&op[oi] = packh(v2, v3);
            }
        }
    }
}

// ====================== O projection (BK=64, SW128 rows, 12 iters) ==========
#define O2_W   8192
#define O2_STG 24576
#define O2_SMEM (3 * O2_STG)   // 73728

__device__ __forceinline__ void o_issue(
    uint32_t stg, const __half* a, const __half* w,
    int row0, int col0, int k0, int tid) {
#pragma unroll
    for (int j = 0; j < 4; j++) {
        int idx = tid + j * 128;
        int r = idx >> 3, ch = idx & 7;
        cp16(stg + SW128(r * 128 + ch * 16),
             a + (size_t)(row0 + r) * DIMC + k0 + ch * 8);
    }
#pragma unroll
    for (int j = 0; j < 8; j++) {
        int idx = tid + j * 128;
        int r = idx >> 3, ch = idx & 7;
        cp16(stg + O2_W + SW128(r * 128 + ch * 16),
             w + (size_t)(col0 + r) * DIMC + k0 + ch * 8);
    }
}

__global__ __launch_bounds__(128, 3)
void proj_o_kernel(const __half* __restrict__ a, const __half* __restrict__ w,
                   const float* __restrict__ bias, float* __restrict__ out) {
    extern __shared__ __align__(16) char dsm[];
    const uint32_t sb = smem_u32(dsm);
    const int tid = threadIdx.x;
    const int wid = tid >> 5;
    const int lane = tid & 31;
    const int wm = wid >> 1;
    const int wn = wid & 1;
    const int row0 = blockIdx.x * 64;
    const int col0 = blockIdx.y * 128;

    float acc[2][8][4];
#pragma unroll
    for (int i = 0; i < 2; i++)
#pragma unroll
        for (int j = 0; j < 8; j++)
#pragma unroll
            for (int k = 0; k < 4; k++) acc[i][j][k] = 0.f;

    const int lrow = (lane & 7) + (lane & 8);
    const int lcb = (lane >> 4) * 16;

    o_issue(sb, a, w, row0, col0, 0, tid);
    CP_COMMIT();
    o_issue(sb + O2_STG, a, w, row0, col0, 64, tid);
    CP_COMMIT();

    for (int kt = 0; kt < 12; kt++) {
        if (kt < 11) { CP_WAIT1(); } else { CP_WAIT0(); }
        __syncthreads();
        if (kt < 10) {
            o_issue(sb + ((kt + 2) % 3) * O2_STG, a, w, row0, col0, (kt + 2) * 64, tid);
            CP_COMMIT();
        }
        const uint32_t stg = sb + (kt % 3) * O2_STG;
#pragma unroll
        for (int ks = 0; ks < 4; ks++) {
            const uint32_t kb = (uint32_t)(ks * 32 + lcb);
            uint32_t af[2][4];
#pragma unroll
            for (int i = 0; i < 2; i++) {
                uint32_t so = SW128((uint32_t)((wm * 32 + i * 16 + lrow) * 128) + kb);
                ldm4(af[i], stg + so);
            }
#pragma unroll
            for (int g = 0; g < 4; g++) {
                uint32_t so = SW128((uint32_t)((wn * 64 + g * 16 + lrow) * 128) + kb);
                uint32_t b4[4];
                ldm4(b4, stg + O2_W + so);
#pragma unroll
                for (int i = 0; i < 2; i++) {
                    mma_f16(acc[i][2 * g],     af[i], b4[0], b4[2]);
                    mma_f16(acc[i][2 * g + 1], af[i], b4[1], b4[3]);
                }
            }
        }
    }

#pragma unroll
    for (int i = 0; i < 2; i++) {
        const int m0 = row0 + wm * 32 + i * 16 + (lane >> 2);
#pragma unroll
        for (int j = 0; j < 8; j++) {
            const int c = col0 + wn * 64 + j * 8 + (lane & 3) * 2;
            float2 bv = *(const float2*)&bias[c];
            float2 r01 = {acc[i][j][0] + bv.x, acc[i][j][1] + bv.y};
            float2 r23 = {acc[i][j][2] + bv.x, acc[i][j][3] + bv.y};
            *(float2*)&out[(size_t)m0 * DIMC + c] = r01;
            *(float2*)&out[(size_t)(m0 + 8) * DIMC + c] = r23;
        }
    }
}

// ====================== attention: 3-stage ring, occ 3 ======================
#define ATILE 8192
#define ASTG  16384
#define AT_SMEM (3 * ASTG)     // 49152

__device__ __forceinline__ void attn_issue_tile(
    uint32_t tilebase, const __half* src, int tid) {
#pragma unroll
    for (int j = 0; j < 4; j++) {
        int idx = tid + j * 128;
        int r = idx >> 3, ch = idx & 7;
        cp16(tilebase + SW128(r * 128 + ch * 16), src + (size_t)r * HD + ch * 8);
    }
}

__global__ __launch_bounds__(128, 3)
void attn_kernel(const __half* __restrict__ q, const __half* __restrict__ k,
                 const __half* __restrict__ v, __half* __restrict__ o) {
    extern __shared__ __align__(16) char dsm[];
    const uint32_t sb = smem_u32(dsm);
    const int tid = threadIdx.x;
    const int w = tid >> 5;
    const int lane = tid & 31;
    const int bh = blockIdx.y;
    const int q0 = blockIdx.x * 128;

    const __half* Q = q + ((size_t)bh * TLEN + q0) * HD;
    const __half* K = k + (size_t)bh * TLEN * HD;
    const __half* V = v + (size_t)bh * TLEN * HD;

    // stage Q (128 rows = 16KB) into stage0, extract fragments
#pragma unroll
    for (int j = 0; j < 8; j++) {
        int idx = tid + j * 128;
        int r = idx >> 3, ch = idx & 7;
        cp16(sb + SW128(r * 128 + ch * 16), Q + (size_t)r * HD + ch * 8);
    }
    CP_COMMIT();
    CP_WAIT0();
    __syncthreads();

    const int lrow = (lane & 7) + (lane & 8);
    const int lcb = (lane >> 4) * 16;
    uint32_t qa[2][4][4];
#pragma unroll
    for (int rb = 0; rb < 2; rb++)
#pragma unroll
        for (int ks = 0; ks < 4; ks++) {
            uint32_t so = SW128((w * 32 + rb * 16 + lrow) * 128 + ks * 32 + lcb);
            ldm4(qa[rb][ks], sb + so);
        }
    __syncthreads();

    // prologue: KV tiles 0,1
    attn_issue_tile(sb,                 K, tid);
    attn_issue_tile(sb + ATILE,         V, tid);
    CP_COMMIT();
    attn_issue_tile(sb + ASTG,          K + (size_t)64 * HD, tid);
    attn_issue_tile(sb + ASTG + ATILE,  V + (size_t)64 * HD, tid);
    CP_COMMIT();

    float oacc[2][8][4];
    float lacc[2][4];
#pragma unroll
    for (int rb = 0; rb < 2; rb++) {
#pragma unroll
        for (int j = 0; j < 8; j++)
#pragma unroll
            for (int kk = 0; kk < 4; kk++) oacc[rb][j][kk] = 0.f;
#pragma unroll
        for (int kk = 0; kk < 4; kk++) lacc[rb][kk] = 0.f;
    }

    for (int t = 0; t < 32; t++) {
        if (t < 31) { CP_WAIT1(); } else { CP_WAIT0(); }
        __syncthreads();
        if (t < 30) {
            const uint32_t ib = sb + ((t + 2) % 3) * ASTG;
            attn_issue_tile(ib,         K + (size_t)(t + 2) * 64 * HD, tid);
            attn_issue_tile(ib + ATILE, V + (size_t)(t + 2) * 64 * HD, tid);
            CP_COMMIT();
        }
        const uint32_t cK = sb + (t % 3) * ASTG;
        const uint32_t cV = cK + ATILE;

        // S = Q K^T : 32 x 64 per warp
        float sc[2][8][4];
#pragma unroll
        for (int rb = 0; rb < 2; rb++)
#pragma unroll
            for (int j = 0; j < 8; j++)
#pragma unroll
                for (int kk = 0; kk < 4; kk++) sc[rb][j][kk] = 0.f;
#pragma unroll
        for (int ks = 0; ks < 4; ks++) {
            const uint32_t kb = (uint32_t)(ks * 32 + lcb);
#pragma unroll
            for (int g = 0; g < 4; g++) {
                uint32_t so = SW128((g * 16 + lrow) * 128 + kb);
                uint32_t b4[4];
                ldm4(b4, cK + so);
#pragma unroll
                for (int rb = 0; rb < 2; rb++) {
                    mma_f16(sc[rb][2 * g],     qa[rb][ks], b4[0], b4[2]);
                    mma_f16(sc[rb][2 * g + 1], qa[rb][ks], b4[1], b4[3]);
                }
            }
        }

        // p = exp2(s~) in f16x2
        uint32_t ph[2][8][2];
#pragma unroll
        for (int rb = 0; rb < 2; rb++)
#pragma unroll
            for (int j = 0; j < 8; j++) {
                ph[rb][j][0] = ex2_h2(packh(sc[rb][j][0], sc[rb][j][1]));
                ph[rb][j][1] = ex2_h2(packh(sc[rb][j][2], sc[rb][j][3]));
            }

        // O += P V;  lacc += P @ ones
#pragma unroll
        for (int ks2 = 0; ks2 < 4; ks2++) {
            uint32_t pa[2][4];
#pragma unroll
            for (int rb = 0; rb < 2; rb++) {
                pa[rb][0] = ph[rb][2 * ks2][0];
                pa[rb][1] = ph[rb][2 * ks2][1];
                pa[rb][2] = ph[rb][2 * ks2 + 1][0];
                pa[rb][3] = ph[rb][2 * ks2 + 1][1];
            }
#pragma unroll
            for (int g = 0; g < 4; g++) {
                uint32_t so = SW128((ks2 * 16 + lrow) * 128 + g * 32 + lcb);
                uint32_t vf[4];
                ldm4t(vf, cV + so);
#pragma unroll
                for (int rb = 0; rb < 2; rb++) {
                    mma_f16(oacc[rb][2 * g],     pa[rb], vf[0], vf[1]);
                    mma_f16(oacc[rb][2 * g + 1], pa[rb], vf[2], vf[3]);
                }
            }
#pragma unroll
            for (int rb = 0; rb < 2; rb++)
                mma_f16(lacc[rb], pa[rb], ONES_H2, ONES_H2);
        }
    }

    const int b = bh / NH, h = bh % NH;
#pragma unroll
    for (int rb = 0; rb < 2; rb++) {
        const float inv0 = 1.f / lacc[rb][0];
        const float inv1 = 1.f / lacc[rb][2];
        const int qr0 = q0 + w * 32 + rb * 16 + (lane >> 2);
        const int qr1 = qr0 + 8;
        size_t base0 = ((size_t)b * TLEN + qr0) * DIMC + h * HD + (lane & 3) * 2;
        size_t base1 = ((size_t)b * TLEN + qr1) * DIMC + h * HD + (lane & 3) * 2;
#pragma unroll
        for (int g = 0; g < 8; g++) {
            *(uint32_t*)&o[base0 + g * 8] = packh(oacc[rb][g][0] * inv0, oacc[rb][g][1] * inv0);
            *(uint32_t*)&o[base1 + g * 8] = packh(oacc[rb][g][2] * inv1, oacc[rb][g][3] * inv1);
        }
    }
}

// ====================== launch ==============================================
extern "C" void kernel_launch(void* const* d_in, const int* in_sizes, int n_in,
                              void* d_out, int out_size) {
    const float* q_in = (const float*)d_in[0];
    const float* k_in = (const float*)d_in[1];
    const float* v_in = (const float*)d_in[2];
    const float* Wq = (const float*)d_in[3];
    const float* bq = (const float*)d_in[4];
    const float* Wk = (const float*)d_in[5];
    const float* bk = (const float*)d_in[6];
    const float* Wv = (const float*)d_in[7];
    const float* bv = (const float*)d_in[8];
    const float* Wo = (const float*)d_in[9];
    const float* bo = (const float*)d_in[10];
    float* out = (float*)d_out;

    __half *xq, *xk, *xv, *wq, *wk, *wv, *wo, *pq, *pk, *pv, *pa;
    cudaGetSymbolAddress((void**)&xq, g_xq);
    cudaGetSymbolAddress((void**)&xk, g_xk);
    cudaGetSymbolAddress((void**)&xv, g_xv);
    cudaGetSymbolAddress((void**)&wq, g_wq);
    cudaGetSymbolAddress((void**)&wk, g_wk);
    cudaGetSymbolAddress((void**)&wv, g_wv);
    cudaGetSymbolAddress((void**)&wo, g_wo);
    cudaGetSymbolAddress((void**)&pq, g_q);
    cudaGetSymbolAddress((void**)&pk, g_k);
    cudaGetSymbolAddress((void**)&pv, g_v);
    cudaGetSymbolAddress((void**)&pa, g_a);

    cudaFuncSetAttribute(proj_qkv_kernel, cudaFuncAttributeMaxDynamicSharedMemorySize, Q2_SMEM);
    cudaFuncSetAttribute(proj_o_kernel, cudaFuncAttributeMaxDynamicSharedMemorySize, O2_SMEM);
    cudaFuncSetAttribute(attn_kernel, cudaFuncAttributeMaxDynamicSharedMemorySize, AT_SMEM);

    split_all_kernel<<<11520, 256>>>(q_in, k_in, v_in, Wq, Wk, Wv, Wo,
                                     xq, xk, xv, wq, wk, wv, wo);

    dim3 pgrid(MROWS / 128, DIMC / 128, 3);   // 32 x 6 x 3
    proj_qkv_kernel<<<pgrid, 128, Q2_SMEM>>>(xq, xk, xv, wq, wk, wv,
                                             bq, bk, bv, pq, pk, pv);

    dim3 agrid(TLEN / 128, BSZ * NH);          // 16 x 24
    attn_kernel<<<agrid, 128, AT_SMEM>>>(pq, pk, pv, pa);

    dim3 ogrid(MROWS / 64, DIMC / 128);        // 64 x 6 = 384
    proj_o_kernel<<<ogrid, 128, O2_SMEM>>>(pa, wo, bo, out);
}

// round 17
// speedup vs baseline: 1.5575x; 1.5575x over previous
#include <cuda_runtime.h>
#include <cuda_bf16.h>
#include <cuda_fp16.h>
#include <stdint.h>

#define DIMC 768
#define NH 12
#define HD 64
#define BSZ 2
#define TLEN 2048
#define MROWS 4096

// score_scale(0.125) * log2(e)
#define QSCALE 0.180336879f
#define ONES_H2 0x3C003C00u

// ---------------- scratch ----------------
__device__ __half g_xq[MROWS * DIMC];
__device__ __half g_xk[MROWS * DIMC];
__device__ __half g_xv[MROWS * DIMC];
__device__ __half g_wq[DIMC * DIMC], g_wk[DIMC * DIMC], g_wv[DIMC * DIMC];
__device__ __half g_wo[DIMC * DIMC];
__device__ __half g_q[MROWS * DIMC], g_k[MROWS * DIMC], g_v[MROWS * DIMC];  // [b,h,t,d]
__device__ __half g_a[MROWS * DIMC];                           // attn out [b,t,c]

// ---------------- helpers ----------------
__device__ __forceinline__ uint32_t smem_u32(const void* p) {
    uint32_t a;
    asm("{ .reg .u64 t; cvta.to.shared.u64 t, %1; cvt.u32.u64 %0, t; }" : "=r"(a) : "l"(p));
    return a;
}
__device__ __forceinline__ void cp16(uint32_t dst, const void* src) {
    asm volatile("cp.async.cg.shared.global [%0], [%1], 16;" :: "r"(dst), "l"(src) : "memory");
}
#define CP_COMMIT() asm volatile("cp.async.commit_group;" ::: "memory")
#define CP_WAIT0()  asm volatile("cp.async.wait_group 0;" ::: "memory")
#define CP_WAIT1()  asm volatile("cp.async.wait_group 1;" ::: "memory")
__device__ __forceinline__ void ldm4(uint32_t* r, uint32_t addr) {
    asm volatile("ldmatrix.sync.aligned.m8n8.x4.shared.b16 {%0,%1,%2,%3}, [%4];"
        : "=r"(r[0]), "=r"(r[1]), "=r"(r[2]), "=r"(r[3]) : "r"(addr));
}
__device__ __forceinline__ void ldm4t(uint32_t* r, uint32_t addr) {
    asm volatile("ldmatrix.sync.aligned.m8n8.x4.trans.shared.b16 {%0,%1,%2,%3}, [%4];"
        : "=r"(r[0]), "=r"(r[1]), "=r"(r[2]), "=r"(r[3]) : "r"(addr));
}
__device__ __forceinline__ void mma_f16(float* c, const uint32_t* a, uint32_t b0, uint32_t b1) {
    asm volatile("mma.sync.aligned.m16n8k16.row.col.f32.f16.f16.f32 "
        "{%0,%1,%2,%3}, {%4,%5,%6,%7}, {%8,%9}, {%0,%1,%2,%3};"
        : "+f"(c[0]), "+f"(c[1]), "+f"(c[2]), "+f"(c[3])
        : "r"(a[0]), "r"(a[1]), "r"(a[2]), "r"(a[3]), "r"(b0), "r"(b1));
}
__device__ __forceinline__ uint32_t packh(float x, float y) {
    __half2 h = __floats2half2_rn(x, y);
    return *(uint32_t*)&h;
}
__device__ __forceinline__ uint32_t ex2_h2(uint32_t x) {
    uint32_t r;
    asm("ex2.approx.f16x2 %0, %1;" : "=r"(r) : "r"(x));
    return r;
}

#define SW128(o) ((uint32_t)(o) ^ ((((uint32_t)(o)) >> 3) & 0x70))

// ====================== merged split kernel =================================
__global__ __launch_bounds__(256)
void split_all_kernel(const float* __restrict__ q_in, const float* __restrict__ k_in,
                      const float* __restrict__ v_in,
                      const float* __restrict__ Wq, const float* __restrict__ Wk,
                      const float* __restrict__ Wv, const float* __restrict__ Wo,
                      __half* xq, __half* xk, __half* xv,
                      __half* wq, __half* wk, __half* wv, __half* wo) {
    int blk = blockIdx.x;
    const float* s;
    __half* d;
    int i;
    if (blk < 9216) {
        int z = blk / 3072;
        i = (blk % 3072) * 256 + threadIdx.x;
        s = z == 0 ? q_in : z == 1 ? k_in : v_in;
        d = z == 0 ? xq : z == 1 ? xk : xv;
    } else {
        int wb = blk - 9216;
        int z = wb / 576;
        i = (wb % 576) * 256 + threadIdx.x;
        s = z == 0 ? Wq : z == 1 ? Wk : z == 2 ? Wv : Wo;
        d = z == 0 ? wq : z == 1 ? wk : z == 2 ? wv : wo;
    }
    float4 v = ((const float4*)s)[i];
    uint2 o = {packh(v.x, v.y), packh(v.z, v.w)};
    ((uint2*)d)[i] = o;
}

// ====================== QKV projection (fp16 single, occ 3) =================
#define PTILE 10240            // 128 rows x 80 B
#define PSTG  20480            // A | W
#define PSMEM (3 * PSTG)       // 61440

__device__ __forceinline__ void qkv_issue(
    uint32_t stg, const __half* a, const __half* w,
    int row0, int col0, int k0, int tid) {
#pragma unroll
    for (int j = 0; j < 4; j++) {
        int idx = tid + j * 128;
        int r = idx >> 2, ch = idx & 3;
        uint32_t doff = (uint32_t)(r * 80 + ch * 16);
        cp16(stg + doff,         a + (size_t)(row0 + r) * DIMC + k0 + ch * 8);
        cp16(stg + PTILE + doff, w + (size_t)(col0 + r) * DIMC + k0 + ch * 8);
    }
}

__global__ __launch_bounds__(128, 3)
void proj_qkv_kernel(
    const __half* __restrict__ xq, const __half* __restrict__ xk,
    const __half* __restrict__ xv,
    const __half* __restrict__ wq, const __half* __restrict__ wk,
    const __half* __restrict__ wv,
    const float* __restrict__ bq, const float* __restrict__ bk,
    const float* __restrict__ bv,
    __half* __restrict__ oq, __half* __restrict__ ok, __half* __restrict__ ov) {
    extern __shared__ __align__(16) char dsm[];
    const uint32_t sb = smem_u32(dsm);
    const int tid = threadIdx.x;
    const int wid = tid >> 5;
    const int lane = tid & 31;
    const int wm = wid >> 1;
    const int wn = wid & 1;
    const int row0 = blockIdx.x * 128;
    const int col0 = blockIdx.y * 128;
    const int z = blockIdx.z;
    const float oscale = (z == 0) ? QSCALE : 1.f;

    const __half* a  = z == 0 ? xq : z == 1 ? xk : xv;
    const __half* w  = z == 0 ? wq : z == 1 ? wk : wv;
    const float* bias = z == 0 ? bq : z == 1 ? bk : bv;
    __half* op = z == 0 ? oq : z == 1 ? ok : ov;

    float acc[4][8][4];
#pragma unroll
    for (int i = 0; i < 4; i++)
#pragma unroll
        for (int j = 0; j < 8; j++)
#pragma unroll
            for (int k = 0; k < 4; k++) acc[i][j][k] = 0.f;

    const int lrow = (lane & 7) + (lane & 8);
    const int lcb = (lane >> 4) * 16;

    qkv_issue(sb, a, w, row0, col0, 0, tid);
    CP_COMMIT();
    qkv_issue(sb + PSTG, a, w, row0, col0, 32, tid);
    CP_COMMIT();

    for (int kt = 0; kt < 24; kt++) {
        if (kt < 23) { CP_WAIT1(); } else { CP_WAIT0(); }
        __syncthreads();
        if (kt < 22) {
            qkv_issue(sb + ((kt + 2) % 3) * PSTG, a, w, row0, col0, (kt + 2) * 32, tid);
            CP_COMMIT();
        }
        const uint32_t stg = sb + (kt % 3) * PSTG;
#pragma unroll
        for (int ks = 0; ks < 2; ks++) {
            const uint32_t kb = (uint32_t)(ks * 32 + lcb);
            uint32_t af[4][4];
#pragma unroll
            for (int i = 0; i < 4; i++) {
                uint32_t off = (uint32_t)((wm * 64 + i * 16 + lrow) * 80) + kb;
                ldm4(af[i], stg + off);
            }
#pragma unroll
            for (int g = 0; g < 4; g++) {
                uint32_t off = (uint32_t)((wn * 64 + g * 16 + lrow) * 80) + kb;
                uint32_t b4[4];
                ldm4(b4, stg + PTILE + off);
#pragma unroll
                for (int i = 0; i < 4; i++) {
                    mma_f16(acc[i][2 * g],     af[i], b4[0], b4[2]);
                    mma_f16(acc[i][2 * g + 1], af[i], b4[1], b4[3]);
                }
            }
        }
    }

    // epilogue (bias loaded here)
#pragma unroll
    for (int i = 0; i < 4; i++) {
        const int m0 = row0 + wm * 64 + i * 16 + (lane >> 2);
#pragma unroll
        for (int j = 0; j < 8; j++) {
            const int c = col0 + wn * 64 + j * 8 + (lane & 3) * 2;
            const int h = c >> 6, d = c & 63;
            float2 bv2 = *(const float2*)&bias[c];
            float v0 = (acc[i][j][0] + bv2.x) * oscale;
            float v1 = (acc[i][j][1] + bv2.y) * oscale;
            float v2 = (acc[i][j][2] + bv2.x) * oscale;
            float v3 = (acc[i][j][3] + bv2.y) * oscale;
            {
                const int gr = m0, b = gr >> 11, t = gr & 2047;
                size_t oi = (((size_t)b * NH + h) * TLEN + t) * HD + d;
                *(uint32_t*)&op[oi] = packh(v0, v1);
            }
            {
                const int gr = m0 + 8, b = gr >> 11, t = gr & 2047;
                size_t oi = (((size_t)b * NH + h) * TLEN + t) * HD + d;
                *(uint32_t*)&op[oi] = packh(v2, v3);
            }
        }
    }
}

// ====================== O projection (BK=64, SW128 rows, 12 iters) ==========
#define O2_W   8192
#define O2_STG 24576
#define O2_SMEM (3 * O2_STG)   // 73728

__device__ __forceinline__ void o_issue(
    uint32_t stg, const __half* a, const __half* w,
    int row0, int col0, int k0, int tid) {
#pragma unroll
    for (int j = 0; j < 4; j++) {
        int idx = tid + j * 128;
        int r = idx >> 3, ch = idx & 7;
        cp16(stg + SW128(r * 128 + ch * 16),
             a + (size_t)(row0 + r) * DIMC + k0 + ch * 8);
    }
#pragma unroll
    for (int j = 0; j < 8; j++) {
        int idx = tid + j * 128;
        int r = idx >> 3, ch = idx & 7;
        cp16(stg + O2_W + SW128(r * 128 + ch * 16),
             w + (size_t)(col0 + r) * DIMC + k0 + ch * 8);
    }
}

__global__ __launch_bounds__(128, 3)
void proj_o_kernel(const __half* __restrict__ a, const __half* __restrict__ w,
                   const float* __restrict__ bias, float* __restrict__ out) {
    extern __shared__ __align__(16) char dsm[];
    const uint32_t sb = smem_u32(dsm);
    const int tid = threadIdx.x;
    const int wid = tid >> 5;
    const int lane = tid & 31;
    const int wm = wid >> 1;
    const int wn = wid & 1;
    const int row0 = blockIdx.x * 64;
    const int col0 = blockIdx.y * 128;

    float acc[2][8][4];
#pragma unroll
    for (int i = 0; i < 2; i++)
#pragma unroll
        for (int j = 0; j < 8; j++)
#pragma unroll
            for (int k = 0; k < 4; k++) acc[i][j][k] = 0.f;

    const int lrow = (lane & 7) + (lane & 8);
    const int lcb = (lane >> 4) * 16;

    o_issue(sb, a, w, row0, col0, 0, tid);
    CP_COMMIT();
    o_issue(sb + O2_STG, a, w, row0, col0, 64, tid);
    CP_COMMIT();

    for (int kt = 0; kt < 12; kt++) {
        if (kt < 11) { CP_WAIT1(); } else { CP_WAIT0(); }
        __syncthreads();
        if (kt < 10) {
            o_issue(sb + ((kt + 2) % 3) * O2_STG, a, w, row0, col0, (kt + 2) * 64, tid);
            CP_COMMIT();
        }
        const uint32_t stg = sb + (kt % 3) * O2_STG;
#pragma unroll
        for (int ks = 0; ks < 4; ks++) {
            const uint32_t kb = (uint32_t)(ks * 32 + lcb);
            uint32_t af[2][4];
#pragma unroll
            for (int i = 0; i < 2; i++) {
                uint32_t so = SW128((uint32_t)((wm * 32 + i * 16 + lrow) * 128) + kb);
                ldm4(af[i], stg + so);
            }
#pragma unroll
            for (int g = 0; g < 4; g++) {
                uint32_t so = SW128((uint32_t)((wn * 64 + g * 16 + lrow) * 128) + kb);
                uint32_t b4[4];
                ldm4(b4, stg + O2_W + so);
#pragma unroll
                for (int i = 0; i < 2; i++) {
                    mma_f16(acc[i][2 * g],     af[i], b4[0], b4[2]);
                    mma_f16(acc[i][2 * g + 1], af[i], b4[1], b4[3]);
                }
            }
        }
    }

#pragma unroll
    for (int i = 0; i < 2; i++) {
        const int m0 = row0 + wm * 32 + i * 16 + (lane >> 2);
#pragma unroll
        for (int j = 0; j < 8; j++) {
            const int c = col0 + wn * 64 + j * 8 + (lane & 3) * 2;
            float2 bv = *(const float2*)&bias[c];
            float2 r01 = {acc[i][j][0] + bv.x, acc[i][j][1] + bv.y};
            float2 r23 = {acc[i][j][2] + bv.x, acc[i][j][3] + bv.y};
            *(float2*)&out[(size_t)m0 * DIMC + c] = r01;
            *(float2*)&out[(size_t)(m0 + 8) * DIMC + c] = r23;
        }
    }
}

// ====================== attention: 3-stage ring, occ 3 ======================
#define ATILE 8192
#define ASTG  16384
#define AT_SMEM (3 * ASTG)     // 49152

__device__ __forceinline__ void attn_issue_tile(
    uint32_t tilebase, const __half* src, int tid) {
#pragma unroll
    for (int j = 0; j < 4; j++) {
        int idx = tid + j * 128;
        int r = idx >> 3, ch = idx & 7;
        cp16(tilebase + SW128(r * 128 + ch * 16), src + (size_t)r * HD + ch * 8);
    }
}

__global__ __launch_bounds__(128, 3)
void attn_kernel(const __half* __restrict__ q, const __half* __restrict__ k,
                 const __half* __restrict__ v, __half* __restrict__ o) {
    extern __shared__ __align__(16) char dsm[];
    const uint32_t sb = smem_u32(dsm);
    const int tid = threadIdx.x;
    const int w = tid >> 5;
    const int lane = tid & 31;
    const int bh = blockIdx.y;
    const int q0 = blockIdx.x * 128;

    const __half* Q = q + ((size_t)bh * TLEN + q0) * HD;
    const __half* K = k + (size_t)bh * TLEN * HD;
    const __half* V = v + (size_t)bh * TLEN * HD;

    // stage Q (128 rows = 16KB) into stage0, extract fragments
#pragma unroll
    for (int j = 0; j < 8; j++) {
        int idx = tid + j * 128;
        int r = idx >> 3, ch = idx & 7;
        cp16(sb + SW128(r * 128 + ch * 16), Q + (size_t)r * HD + ch * 8);
    }
    CP_COMMIT();
    CP_WAIT0();
    __syncthreads();

    const int lrow = (lane & 7) + (lane & 8);
    const int lcb = (lane >> 4) * 16;
    uint32_t qa[2][4][4];
#pragma unroll
    for (int rb = 0; rb < 2; rb++)
#pragma unroll
        for (int ks = 0; ks < 4; ks++) {
            uint32_t so = SW128((w * 32 + rb * 16 + lrow) * 128 + ks * 32 + lcb);
            ldm4(qa[rb][ks], sb + so);
        }
    __syncthreads();

    // prologue: KV tiles 0,1
    attn_issue_tile(sb,                 K, tid);
    attn_issue_tile(sb + ATILE,         V, tid);
    CP_COMMIT();
    attn_issue_tile(sb + ASTG,          K + (size_t)64 * HD, tid);
    attn_issue_tile(sb + ASTG + ATILE,  V + (size_t)64 * HD, tid);
    CP_COMMIT();

    float oacc[2][8][4];
    float lacc[2][4];
#pragma unroll
    for (int rb = 0; rb < 2; rb++) {
#pragma unroll
        for (int j = 0; j < 8; j++)
#pragma unroll
            for (int kk = 0; kk < 4; kk++) oacc[rb][j][kk] = 0.f;
#pragma unroll
        for (int kk = 0; kk < 4; kk++) lacc[rb][kk] = 0.f;
    }

    for (int t = 0; t < 32; t++) {
        if (t < 31) { CP_WAIT1(); } else { CP_WAIT0(); }
        __syncthreads();
        if (t < 30) {
            const uint32_t ib = sb + ((t + 2) % 3) * ASTG;
            attn_issue_tile(ib,         K + (size_t)(t + 2) * 64 * HD, tid);
            attn_issue_tile(ib + ATILE, V + (size_t)(t + 2) * 64 * HD, tid);
            CP_COMMIT();
        }
        const uint32_t cK = sb + (t % 3) * ASTG;
        const uint32_t cV = cK + ATILE;

        // S = Q K^T : 32 x 64 per warp
        float sc[2][8][4];
#pragma unroll
        for (int rb = 0; rb < 2; rb++)
#pragma unroll
            for (int j = 0; j < 8; j++)
#pragma unroll
                for (int kk = 0; kk < 4; kk++) sc[rb][j][kk] = 0.f;
#pragma unroll
        for (int ks = 0; ks < 4; ks++) {
            const uint32_t kb = (uint32_t)(ks * 32 + lcb);
#pragma unroll
            for (int g = 0; g < 4; g++) {
                uint32_t so = SW128((g * 16 + lrow) * 128 + kb);
                uint32_t b4[4];
                ldm4(b4, cK + so);
#pragma unroll
                for (int rb = 0; rb < 2; rb++) {
                    mma_f16(sc[rb][2 * g],     qa[rb][ks], b4[0], b4[2]);
                    mma_f16(sc[rb][2 * g + 1], qa[rb][ks], b4[1], b4[3]);
                }
            }
        }

        // p = exp2(s~) in f16x2
        uint32_t ph[2][8][2];
#pragma unroll
        for (int rb = 0; rb < 2; rb++)
#pragma unroll
            for (int j = 0; j < 8; j++) {
                ph[rb][j][0] = ex2_h2(packh(sc[rb][j][0], sc[rb][j][1]));
                ph[rb][j][1] = ex2_h2(packh(sc[rb][j][2], sc[rb][j][3]));
            }

        // O += P V;  lacc += P @ ones
#pragma unroll
        for (int ks2 = 0; ks2 < 4; ks2++) {
            uint32_t pa[2][4];
#pragma unroll
            for (int rb = 0; rb < 2; rb++) {
                pa[rb][0] = ph[rb][2 * ks2][0];
                pa[rb][1] = ph[rb][2 * ks2][1];
                pa[rb][2] = ph[rb][2 * ks2 + 1][0];
                pa[rb][3] = ph[rb][2 * ks2 + 1][1];
            }
#pragma unroll
            for (int g = 0; g < 4; g++) {
                uint32_t so = SW128((ks2 * 16 + lrow) * 128 + g * 32 + lcb);
                uint32_t vf[4];
                ldm4t(vf, cV + so);
#pragma unroll
                for (int rb = 0; rb < 2; rb++) {
                    mma_f16(oacc[rb][2 * g],     pa[rb], vf[0], vf[1]);
                    mma_f16(oacc[rb][2 * g + 1], pa[rb], vf[2], vf[3]);
                }
            }
#pragma unroll
            for (int rb = 0; rb < 2; rb++)
                mma_f16(lacc[rb], pa[rb], ONES_H2, ONES_H2);
        }
    }

    const int b = bh / NH, h = bh % NH;
#pragma unroll
    for (int rb = 0; rb < 2; rb++) {
        const float inv0 = 1.f / lacc[rb][0];
        const float inv1 = 1.f / lacc[rb][2];
        const int qr0 = q0 + w * 32 + rb * 16 + (lane >> 2);
        const int qr1 = qr0 + 8;
        size_t base0 = ((size_t)b * TLEN + qr0) * DIMC + h * HD + (lane & 3) * 2;
        size_t base1 = ((size_t)b * TLEN + qr1) * DIMC + h * HD + (lane & 3) * 2;
#pragma unroll
        for (int g = 0; g < 8; g++) {
            *(uint32_t*)&o[base0 + g * 8] = packh(oacc[rb][g][0] * inv0, oacc[rb][g][1] * inv0);
            *(uint32_t*)&o[base1 + g * 8] = packh(oacc[rb][g][2] * inv1, oacc[rb][g][3] * inv1);
        }
    }
}

// ====================== launch ==============================================
extern "C" void kernel_launch(void* const* d_in, const int* in_sizes, int n_in,
                              void* d_out, int out_size) {
    const float* q_in = (const float*)d_in[0];
    const float* k_in = (const float*)d_in[1];
    const float* v_in = (const float*)d_in[2];
    const float* Wq = (const float*)d_in[3];
    const float* bq = (const float*)d_in[4];
    const float* Wk = (const float*)d_in[5];
    const float* bk = (const float*)d_in[6];
    const float* Wv = (const float*)d_in[7];
    const float* bv = (const float*)d_in[8];
    const float* Wo = (const float*)d_in[9];
    const float* bo = (const float*)d_in[10];
    float* out = (float*)d_out;

    __half *xq, *xk, *xv, *wq, *wk, *wv, *wo, *pq, *pk, *pv, *pa;
    cudaGetSymbolAddress((void**)&xq, g_xq);
    cudaGetSymbolAddress((void**)&xk, g_xk);
    cudaGetSymbolAddress((void**)&xv, g_xv);
    cudaGetSymbolAddress((void**)&wq, g_wq);
    cudaGetSymbolAddress((void**)&wk, g_wk);
    cudaGetSymbolAddress((void**)&wv, g_wv);
    cudaGetSymbolAddress((void**)&wo, g_wo);
    cudaGetSymbolAddress((void**)&pq, g_q);
    cudaGetSymbolAddress((void**)&pk, g_k);
    cudaGetSymbolAddress((void**)&pv, g_v);
    cudaGetSymbolAddress((void**)&pa, g_a);

    cudaFuncSetAttribute(proj_qkv_kernel, cudaFuncAttributeMaxDynamicSharedMemorySize, PSMEM);
    cudaFuncSetAttribute(proj_o_kernel, cudaFuncAttributeMaxDynamicSharedMemorySize, O2_SMEM);
    cudaFuncSetAttribute(attn_kernel, cudaFuncAttributeMaxDynamicSharedMemorySize, AT_SMEM);

    split_all_kernel<<<11520, 256>>>(q_in, k_in, v_in, Wq, Wk, Wv, Wo,
                                     xq, xk, xv, wq, wk, wv, wo);

    dim3 pgrid(MROWS / 128, DIMC / 128, 3);   // 32 x 6 x 3
    proj_qkv_kernel<<<pgrid, 128, PSMEM>>>(xq, xk, xv, wq, wk, wv,
                                           bq, bk, bv, pq, pk, pv);

    dim3 agrid(TLEN / 128, BSZ * NH);          // 16 x 24
    attn_kernel<<<agrid, 128, AT_SMEM>>>(pq, pk, pv, pa);

    dim3 ogrid(MROWS / 64, DIMC / 128);        // 64 x 6 = 384
    proj_o_kernel<<<ogrid, 128, O2_SMEM>>>(pa, wo, bo, out);
}